// round 1
// baseline (speedup 1.0000x reference)
#include <cuda_runtime.h>
#include <math.h>

#define B_ROWS 64
#define N_PTS 1024
#define HID 256
#define EPB 16          // elements per block in MLP GEMM
#define PROM_MIN 0.1f

// scratch: normalized time (graph-safe __device__ global, no allocs)
__device__ float g_tn[B_ROWS * N_PTS];

// ---------------------------------------------------------------------------
// Kernel 1: per-row min/max + normalize. 64 blocks x 256 threads.
// ---------------------------------------------------------------------------
__global__ void tn_kernel(const float* __restrict__ tp, float* __restrict__ tn)
{
    __shared__ float smin[256];
    __shared__ float smax[256];
    int row = blockIdx.x;
    int tid = threadIdx.x;
    const float* x = tp + row * N_PTS;

    float mn = INFINITY, mx = -INFINITY;
    #pragma unroll
    for (int i = tid; i < N_PTS; i += 256) {
        float v = x[i];
        mn = fminf(mn, v);
        mx = fmaxf(mx, v);
    }
    smin[tid] = mn; smax[tid] = mx;
    __syncthreads();
    for (int s = 128; s > 0; s >>= 1) {
        if (tid < s) {
            smin[tid] = fminf(smin[tid], smin[tid + s]);
            smax[tid] = fmaxf(smax[tid], smax[tid + s]);
        }
        __syncthreads();
    }
    float tmin = smin[0];
    float tr   = fmaxf(smax[0] - tmin, 1e-6f);
    float inv  = 1.0f / tr;
    #pragma unroll
    for (int i = tid; i < N_PTS; i += 256) {
        tn[row * N_PTS + i] = (x[i] - tmin) * inv;
    }
}

// ---------------------------------------------------------------------------
// Kernel 2: MLP. Each block: EPB=16 points, 256 threads (one per hidden j).
//   h1[e][k] = relu(tn*W1[k] + b1[k])       (smem tile, 16KB)
//   h2[e][j] = relu(sum_k h1[e][k]*W2[k][j] + b2[j])
//   y[e]     = softplus(sum_j h2[e][j]*W3[j] + b3)
// W2 row-major (k, j) -> coalesced LDG across j, L2-resident (256KB).
// ---------------------------------------------------------------------------
__global__ void mlp_kernel(const float* __restrict__ tn,
                           const float* __restrict__ W1, const float* __restrict__ b1,
                           const float* __restrict__ W2, const float* __restrict__ b2,
                           const float* __restrict__ W3, const float* __restrict__ b3,
                           float* __restrict__ out)
{
    __shared__ float h1s[EPB][HID];   // 16 KB
    int tid  = threadIdx.x;
    int base = blockIdx.x * EPB;

    // build h1 tile
    #pragma unroll
    for (int idx = tid; idx < EPB * HID; idx += 256) {
        int e = idx >> 8;
        int k = idx & 255;
        float t = tn[base + e];
        h1s[e][k] = fmaxf(fmaf(t, W1[k], b1[k]), 0.0f);
    }
    __syncthreads();

    int j = tid;
    float bj = b2[j];
    float acc[EPB];
    #pragma unroll
    for (int e = 0; e < EPB; e++) acc[e] = bj;

    #pragma unroll 4
    for (int k = 0; k < HID; k += 4) {
        float w0 = W2[(k + 0) * HID + j];
        float w1 = W2[(k + 1) * HID + j];
        float w2 = W2[(k + 2) * HID + j];
        float w3 = W2[(k + 3) * HID + j];
        #pragma unroll
        for (int e = 0; e < EPB; e++) {
            float4 h = *reinterpret_cast<const float4*>(&h1s[e][k]);
            acc[e] = fmaf(h.x, w0, acc[e]);
            acc[e] = fmaf(h.y, w1, acc[e]);
            acc[e] = fmaf(h.z, w2, acc[e]);
            acc[e] = fmaf(h.w, w3, acc[e]);
        }
    }

    float w3j = W3[j];
    __syncthreads();
    #pragma unroll
    for (int e = 0; e < EPB; e++)
        h1s[e][tid] = fmaxf(acc[e], 0.0f) * w3j;   // relu(h2)*W3[j]
    __syncthreads();

    // tree-reduce 256 -> 1 for all 16 elements
    for (int s = 128; s > 0; s >>= 1) {
        if (tid < s) {
            #pragma unroll
            for (int e = 0; e < EPB; e++)
                h1s[e][tid] += h1s[e][tid + s];
        }
        __syncthreads();
    }
    if (tid < EPB) {
        float v = h1s[tid][0] + b3[0];
        // softplus = max(v,0) + log1p(exp(-|v|))
        float sp = fmaxf(v, 0.0f) + log1pf(expf(-fabsf(v)));
        out[base + tid] = sp;
    }
}

// ---------------------------------------------------------------------------
// Kernel 3: per-row peak/prominence + top-K select. 64 blocks x 256 threads.
// ---------------------------------------------------------------------------
__global__ void select_kernel(const float* __restrict__ density,
                              float* __restrict__ out_idx, int K)
{
    __shared__ float xs[N_PTS];
    __shared__ float score[N_PTS];
    __shared__ float rv[256];
    __shared__ int   ri[256];
    __shared__ int   sel[64];
    __shared__ int   s_count;

    int row = blockIdx.x;
    int tid = threadIdx.x;
    const float* x = density + row * N_PTS;

    #pragma unroll
    for (int i = tid; i < N_PTS; i += 256) xs[i] = x[i];
    if (tid == 0) s_count = 0;
    __syncthreads();

    // prominence per index (brute scan in smem; higher = strict '>')
    for (int i = tid; i < N_PTS; i += 256) {
        float xi = xs[i];
        float lm = xi;
        for (int j = i - 1; j >= 0; j--) {
            float v = xs[j];
            if (v > xi) break;
            lm = fminf(lm, v);
        }
        float rm = xi;
        for (int j = i + 1; j < N_PTS; j++) {
            float v = xs[j];
            if (v > xi) break;
            rm = fminf(rm, v);
        }
        float prom = xi - fmaxf(lm, rm);
        bool peak  = (i > 0) && (i < N_PTS - 1) && (xi > xs[i - 1]) && (xi > xs[i + 1]);
        bool valid = peak && (prom >= PROM_MIN);
        score[i] = valid ? prom : -INFINITY;
        if (valid) atomicAdd(&s_count, 1);
    }
    __syncthreads();

    bool useA = (s_count >= K);
    if (!useA) {
        for (int i = tid; i < N_PTS; i += 256) score[i] = xs[i];
        __syncthreads();
    }

    // iterative top-K: K x block-argmax (tie -> smaller index, matches top_k)
    for (int it = 0; it < K; it++) {
        float bv = -INFINITY;
        int   bi = N_PTS;
        for (int i = tid; i < N_PTS; i += 256) {
            float v = score[i];
            if (v > bv || (v == bv && i < bi)) { bv = v; bi = i; }
        }
        rv[tid] = bv; ri[tid] = bi;
        __syncthreads();
        for (int s = 128; s > 0; s >>= 1) {
            if (tid < s) {
                float v = rv[tid + s];
                int   ii = ri[tid + s];
                if (v > rv[tid] || (v == rv[tid] && ii < ri[tid])) {
                    rv[tid] = v; ri[tid] = ii;
                }
            }
            __syncthreads();
        }
        if (tid == 0) {
            sel[it] = ri[0];
            score[ri[0]] = -INFINITY;
        }
        __syncthreads();
    }

    if (tid == 0) {
        // insertion sort ascending
        for (int a = 1; a < K; a++) {
            int v = sel[a], b = a - 1;
            while (b >= 0 && sel[b] > v) { sel[b + 1] = sel[b]; b--; }
            sel[b + 1] = v;
        }
        for (int a = 0; a < K; a++)
            out_idx[row * K + a] = (float)sel[a];
    }
}

// ---------------------------------------------------------------------------
// launch
// ---------------------------------------------------------------------------
extern "C" void kernel_launch(void* const* d_in, const int* in_sizes, int n_in,
                              void* d_out, int out_size)
{
    const float* time_points = (const float*)d_in[0];
    // d_in[1] = num_gen_points (scalar); K derived from out layout instead
    const float* W1 = (const float*)d_in[2];
    const float* b1 = (const float*)d_in[3];
    const float* W2 = (const float*)d_in[4];
    const float* b2 = (const float*)d_in[5];
    const float* W3 = (const float*)d_in[6];
    const float* b3 = (const float*)d_in[7];

    float* out = (float*)d_out;
    float* out_density = out;                       // B*N floats
    float* out_indices = out + B_ROWS * N_PTS;      // B*K floats

    int K = (out_size - B_ROWS * N_PTS) / B_ROWS;
    if (K < 1) K = 16;
    if (K > 64) K = 64;

    float* tn;
    cudaGetSymbolAddress((void**)&tn, g_tn);

    tn_kernel<<<B_ROWS, 256>>>(time_points, tn);
    mlp_kernel<<<(B_ROWS * N_PTS) / EPB, 256>>>(tn, W1, b1, W2, b2, W3, b3, out_density);
    select_kernel<<<B_ROWS, 256>>>(out_density, out_indices, K);
}

// round 2
// speedup vs baseline: 2.8429x; 2.8429x over previous
#include <cuda_runtime.h>
#include <math.h>

#define B_ROWS 64
#define N_PTS 1024
#define HID 256
#define EPB 16
#define PROM_MIN 0.1f

// graph-safe scratch
__device__ float g_tn[B_ROWS * N_PTS];
__device__ float g_c;
__device__ int   g_fast;   // 1 => bias-zero fast path valid

// ---------------------------------------------------------------------------
// Kernel 0: validate b1==0 && b2==0; compute c = sum_j relu(u_j)*W3[j],
//           u_j = sum_k relu(W1[k]) * W2[k][j].   1 block x 256 threads.
// ---------------------------------------------------------------------------
__global__ void setup_kernel(const float* __restrict__ W1, const float* __restrict__ b1,
                             const float* __restrict__ W2, const float* __restrict__ b2,
                             const float* __restrict__ W3)
{
    __shared__ float w1r[HID];
    __shared__ float red[HID];
    __shared__ int   nz;
    int j = threadIdx.x;
    if (j == 0) nz = 0;
    __syncthreads();
    if (b1[j] != 0.0f || b2[j] != 0.0f) atomicAdd(&nz, 1);
    w1r[j] = fmaxf(W1[j], 0.0f);
    __syncthreads();

    float u = 0.0f;
    #pragma unroll 8
    for (int k = 0; k < HID; k++)
        u = fmaf(w1r[k], W2[k * HID + j], u);   // coalesced across j
    red[j] = fmaxf(u, 0.0f) * W3[j];
    __syncthreads();
    for (int s = 128; s > 0; s >>= 1) {
        if (j < s) red[j] += red[j + s];
        __syncthreads();
    }
    if (j == 0) {
        g_c = red[0];
        g_fast = (nz == 0) ? 1 : 0;
    }
}

// ---------------------------------------------------------------------------
// Kernel 1: per-row min/max + normalize. 64 blocks x 256 threads.
// ---------------------------------------------------------------------------
__global__ void tn_kernel(const float* __restrict__ tp, float* __restrict__ tn)
{
    __shared__ float smin[256];
    __shared__ float smax[256];
    int row = blockIdx.x;
    int tid = threadIdx.x;
    const float* x = tp + row * N_PTS;

    float mn = INFINITY, mx = -INFINITY;
    #pragma unroll
    for (int i = tid; i < N_PTS; i += 256) {
        float v = x[i];
        mn = fminf(mn, v);
        mx = fmaxf(mx, v);
    }
    smin[tid] = mn; smax[tid] = mx;
    __syncthreads();
    for (int s = 128; s > 0; s >>= 1) {
        if (tid < s) {
            smin[tid] = fminf(smin[tid], smin[tid + s]);
            smax[tid] = fmaxf(smax[tid], smax[tid + s]);
        }
        __syncthreads();
    }
    float tmin = smin[0];
    float tr   = fmaxf(smax[0] - tmin, 1e-6f);
    float inv  = 1.0f / tr;
    #pragma unroll
    for (int i = tid; i < N_PTS; i += 256) {
        tn[row * N_PTS + i] = (x[i] - tmin) * inv;
    }
}

// ---------------------------------------------------------------------------
// Kernel 2a: fast path — density = softplus(c * t + b3). 256 blocks x 256 thr.
// ---------------------------------------------------------------------------
__global__ void fast_density_kernel(const float* __restrict__ tn,
                                    const float* __restrict__ b3,
                                    float* __restrict__ out)
{
    if (!g_fast) return;
    int i = blockIdx.x * blockDim.x + threadIdx.x;
    float v = fmaf(g_c, tn[i], b3[0]);
    out[i] = fmaxf(v, 0.0f) + log1pf(expf(-fabsf(v)));
}

// ---------------------------------------------------------------------------
// Kernel 2b: fallback full MLP (early-exits when fast path valid).
// ---------------------------------------------------------------------------
__global__ void mlp_kernel(const float* __restrict__ tn,
                           const float* __restrict__ W1, const float* __restrict__ b1,
                           const float* __restrict__ W2, const float* __restrict__ b2,
                           const float* __restrict__ W3, const float* __restrict__ b3,
                           float* __restrict__ out)
{
    if (g_fast) return;
    __shared__ float h1s[EPB][HID];
    int tid  = threadIdx.x;
    int base = blockIdx.x * EPB;

    #pragma unroll
    for (int idx = tid; idx < EPB * HID; idx += 256) {
        int e = idx >> 8;
        int k = idx & 255;
        float t = tn[base + e];
        h1s[e][k] = fmaxf(fmaf(t, W1[k], b1[k]), 0.0f);
    }
    __syncthreads();

    int j = tid;
    float bj = b2[j];
    float acc[EPB];
    #pragma unroll
    for (int e = 0; e < EPB; e++) acc[e] = bj;

    #pragma unroll 4
    for (int k = 0; k < HID; k += 4) {
        float w0 = W2[(k + 0) * HID + j];
        float w1 = W2[(k + 1) * HID + j];
        float w2 = W2[(k + 2) * HID + j];
        float w3 = W2[(k + 3) * HID + j];
        #pragma unroll
        for (int e = 0; e < EPB; e++) {
            float4 h = *reinterpret_cast<const float4*>(&h1s[e][k]);
            acc[e] = fmaf(h.x, w0, acc[e]);
            acc[e] = fmaf(h.y, w1, acc[e]);
            acc[e] = fmaf(h.z, w2, acc[e]);
            acc[e] = fmaf(h.w, w3, acc[e]);
        }
    }

    float w3j = W3[j];
    __syncthreads();
    #pragma unroll
    for (int e = 0; e < EPB; e++)
        h1s[e][tid] = fmaxf(acc[e], 0.0f) * w3j;
    __syncthreads();

    for (int s = 128; s > 0; s >>= 1) {
        if (tid < s) {
            #pragma unroll
            for (int e = 0; e < EPB; e++)
                h1s[e][tid] += h1s[e][tid + s];
        }
        __syncthreads();
    }
    if (tid < EPB) {
        float v = h1s[tid][0] + b3[0];
        float sp = fmaxf(v, 0.0f) + log1pf(expf(-fabsf(v)));
        out[base + tid] = sp;
    }
}

// ---------------------------------------------------------------------------
// Kernel 3: per-row peak/prominence + top-K select. 64 blocks x 256 threads.
// ---------------------------------------------------------------------------
__global__ void select_kernel(const float* __restrict__ density,
                              float* __restrict__ out_idx, int K)
{
    __shared__ float xs[N_PTS];
    __shared__ float score[N_PTS];
    __shared__ float rv[256];
    __shared__ int   ri[256];
    __shared__ int   sel[64];
    __shared__ int   s_count;

    int row = blockIdx.x;
    int tid = threadIdx.x;
    const float* x = density + row * N_PTS;

    #pragma unroll
    for (int i = tid; i < N_PTS; i += 256) xs[i] = x[i];
    if (tid == 0) s_count = 0;
    __syncthreads();

    for (int i = tid; i < N_PTS; i += 256) {
        float xi = xs[i];
        float lm = xi;
        for (int j = i - 1; j >= 0; j--) {
            float v = xs[j];
            if (v > xi) break;
            lm = fminf(lm, v);
        }
        float rm = xi;
        for (int j = i + 1; j < N_PTS; j++) {
            float v = xs[j];
            if (v > xi) break;
            rm = fminf(rm, v);
        }
        float prom = xi - fmaxf(lm, rm);
        bool peak  = (i > 0) && (i < N_PTS - 1) && (xi > xs[i - 1]) && (xi > xs[i + 1]);
        bool valid = peak && (prom >= PROM_MIN);
        score[i] = valid ? prom : -INFINITY;
        if (valid) atomicAdd(&s_count, 1);
    }
    __syncthreads();

    bool useA = (s_count >= K);
    if (!useA) {
        for (int i = tid; i < N_PTS; i += 256) score[i] = xs[i];
        __syncthreads();
    }

    for (int it = 0; it < K; it++) {
        float bv = -INFINITY;
        int   bi = N_PTS;
        for (int i = tid; i < N_PTS; i += 256) {
            float v = score[i];
            if (v > bv || (v == bv && i < bi)) { bv = v; bi = i; }
        }
        rv[tid] = bv; ri[tid] = bi;
        __syncthreads();
        for (int s = 128; s > 0; s >>= 1) {
            if (tid < s) {
                float v = rv[tid + s];
                int   ii = ri[tid + s];
                if (v > rv[tid] || (v == rv[tid] && ii < ri[tid])) {
                    rv[tid] = v; ri[tid] = ii;
                }
            }
            __syncthreads();
        }
        if (tid == 0) {
            sel[it] = ri[0];
            score[ri[0]] = -INFINITY;
        }
        __syncthreads();
    }

    if (tid == 0) {
        for (int a = 1; a < K; a++) {
            int v = sel[a], b = a - 1;
            while (b >= 0 && sel[b] > v) { sel[b + 1] = sel[b]; b--; }
            sel[b + 1] = v;
        }
        for (int a = 0; a < K; a++)
            out_idx[row * K + a] = (float)sel[a];
    }
}

// ---------------------------------------------------------------------------
extern "C" void kernel_launch(void* const* d_in, const int* in_sizes, int n_in,
                              void* d_out, int out_size)
{
    const float* time_points = (const float*)d_in[0];
    const float* W1 = (const float*)d_in[2];
    const float* b1 = (const float*)d_in[3];
    const float* W2 = (const float*)d_in[4];
    const float* b2 = (const float*)d_in[5];
    const float* W3 = (const float*)d_in[6];
    const float* b3 = (const float*)d_in[7];

    float* out = (float*)d_out;
    float* out_density = out;
    float* out_indices = out + B_ROWS * N_PTS;

    int K = (out_size - B_ROWS * N_PTS) / B_ROWS;
    if (K < 1) K = 16;
    if (K > 64) K = 64;

    float* tn;
    cudaGetSymbolAddress((void**)&tn, g_tn);

    setup_kernel<<<1, 256>>>(W1, b1, W2, b2, W3);
    tn_kernel<<<B_ROWS, 256>>>(time_points, tn);
    fast_density_kernel<<<(B_ROWS * N_PTS) / 256, 256>>>(tn, b3, out_density);
    mlp_kernel<<<(B_ROWS * N_PTS) / EPB, 256>>>(tn, W1, b1, W2, b2, W3, b3, out_density);
    select_kernel<<<B_ROWS, 256>>>(out_density, out_indices, K);
}

// round 3
// speedup vs baseline: 9.0928x; 3.1984x over previous
#include <cuda_runtime.h>
#include <math.h>

#define B_ROWS 64
#define N_PTS 1024
#define HID 256
#define EPB 16
#define KMAX 64
#define PROM_MIN 0.1f

__device__ float g_tn[B_ROWS * N_PTS];
__device__ float g_c;
__device__ int   g_fast;

// float -> order-preserving unsigned
__device__ __forceinline__ unsigned ordf(float f) {
    unsigned u = __float_as_uint(f);
    return (u & 0x80000000u) ? ~u : (u | 0x80000000u);
}

// ---------------------------------------------------------------------------
// Shared scratch for the select core
// ---------------------------------------------------------------------------
struct SelShared {
    float xs[N_PTS];
    float cmax[32];
    float cmin[32];
    unsigned long long blk[KMAX];
    int   cnt;
};

// ---------------------------------------------------------------------------
// select core: xs[] already filled. 256 threads. Writes K sorted indices.
// ---------------------------------------------------------------------------
__device__ __forceinline__ void select_core(SelShared* s, float* out_idx_row, int K)
{
    int tid  = threadIdx.x;
    int w    = tid >> 5;
    int lane = tid & 31;

    // chunk stats: warp w handles chunks 4w..4w+3
    #pragma unroll
    for (int cc = 0; cc < 4; cc++) {
        int c = w * 4 + cc;
        float v = s->xs[c * 32 + lane];
        float mx = v, mn = v;
        #pragma unroll
        for (int o = 16; o; o >>= 1) {
            mx = fmaxf(mx, __shfl_xor_sync(0xffffffffu, mx, o));
            mn = fminf(mn, __shfl_xor_sync(0xffffffffu, mn, o));
        }
        if (lane == 0) { s->cmax[c] = mx; s->cmin[c] = mn; }
    }
    if (tid == 0) s->cnt = 0;
    for (int it = tid; it < KMAX; it += 256) s->blk[it] = 0ULL;
    __syncthreads();

    float xv[4], promv[4];
    bool  validv[4];
    int   localcnt = 0;

    #pragma unroll
    for (int sgi = 0; sgi < 4; sgi++) {
        int i = tid + 256 * sgi;
        float xi = s->xs[i];
        xv[sgi] = xi;

        // left scan
        float lm = xi;
        bool stopped = false;
        int cstart = i & ~31;
        for (int j = i - 1; j >= cstart; j--) {
            float v = s->xs[j];
            if (v > xi) { stopped = true; break; }
            lm = fminf(lm, v);
        }
        if (!stopped) {
            int c = (i >> 5) - 1;
            for (; c >= 0; c--) {
                if (s->cmax[c] > xi) break;
                lm = fminf(lm, s->cmin[c]);
            }
            if (c >= 0) {
                for (int j = c * 32 + 31; ; j--) {
                    float v = s->xs[j];
                    if (v > xi) break;
                    lm = fminf(lm, v);
                }
            }
        }
        // right scan
        float rm = xi;
        stopped = false;
        int cend = i | 31;
        for (int j = i + 1; j <= cend; j++) {
            float v = s->xs[j];
            if (v > xi) { stopped = true; break; }
            rm = fminf(rm, v);
        }
        if (!stopped) {
            int c = (i >> 5) + 1;
            for (; c < 32; c++) {
                if (s->cmax[c] > xi) break;
                rm = fminf(rm, s->cmin[c]);
            }
            if (c < 32) {
                for (int j = c * 32; ; j++) {
                    float v = s->xs[j];
                    if (v > xi) break;
                    rm = fminf(rm, v);
                }
            }
        }

        float prom = xi - fmaxf(lm, rm);
        bool peak  = (i > 0) && (i < N_PTS - 1) &&
                     (xi > s->xs[i - 1]) && (xi > s->xs[i + 1]);
        bool valid = peak && (prom >= PROM_MIN);
        promv[sgi]  = prom;
        validv[sgi] = valid;
        if (valid) localcnt++;
    }
    if (localcnt) atomicAdd(&s->cnt, localcnt);
    __syncthreads();

    bool useA = (s->cnt >= K);
    unsigned long long key[4];
    #pragma unroll
    for (int sgi = 0; sgi < 4; sgi++) {
        int i = tid + 256 * sgi;
        float sc = useA ? (validv[sgi] ? promv[sgi] : -INFINITY) : xv[sgi];
        key[sgi] = ((unsigned long long)ordf(sc) << 32) | (unsigned)(~(unsigned)i);
    }

    // K rounds: one atomicMax + one sync each (fresh slot per round)
    for (int it = 0; it < K; it++) {
        unsigned long long b = key[0];
        if (key[1] > b) b = key[1];
        if (key[2] > b) b = key[2];
        if (key[3] > b) b = key[3];
        atomicMax(&s->blk[it], b);
        __syncthreads();
        unsigned widx = ~(unsigned)(s->blk[it] & 0xffffffffULL);
        #pragma unroll
        for (int sgi = 0; sgi < 4; sgi++)
            if ((unsigned)(tid + 256 * sgi) == widx) key[sgi] = 0ULL;
    }

    if (tid == 0) {
        int sel[KMAX];
        for (int it = 0; it < K; it++)
            sel[it] = (int)(~(unsigned)(s->blk[it] & 0xffffffffULL));
        for (int a = 1; a < K; a++) {
            int v = sel[a], b = a - 1;
            while (b >= 0 && sel[b] > v) { sel[b + 1] = sel[b]; b--; }
            sel[b + 1] = v;
        }
        for (int a = 0; a < K; a++) out_idx_row[a] = (float)sel[a];
    }
}

// ---------------------------------------------------------------------------
// Kernel 0: validate biases, compute scalar c. 1 block x 1024 threads.
// ---------------------------------------------------------------------------
__global__ void setup_kernel(const float* __restrict__ W1, const float* __restrict__ b1,
                             const float* __restrict__ W2, const float* __restrict__ b2,
                             const float* __restrict__ W3)
{
    __shared__ float w1r[HID];
    __shared__ float ps[4][HID];
    __shared__ float red[HID];
    __shared__ int   nz;
    int tid = threadIdx.x;
    if (tid == 0) nz = 0;
    if (tid < HID) w1r[tid] = fmaxf(W1[tid], 0.0f);
    __syncthreads();
    if (tid < HID) {
        if (b1[tid] != 0.0f || b2[tid] != 0.0f) atomicAdd(&nz, 1);
    }
    int j = tid & 255;
    int p = tid >> 8;
    float u = 0.0f;
    int k0 = p * 64;
    #pragma unroll 8
    for (int k = k0; k < k0 + 64; k++)
        u = fmaf(w1r[k], W2[k * HID + j], u);
    ps[p][j] = u;
    __syncthreads();
    if (tid < HID) {
        float U = ps[0][tid] + ps[1][tid] + ps[2][tid] + ps[3][tid];
        red[tid] = fmaxf(U, 0.0f) * W3[tid];
    }
    __syncthreads();
    for (int st = 128; st > 0; st >>= 1) {
        if (tid < st) red[tid] += red[tid + st];
        __syncthreads();
    }
    if (tid == 0) {
        g_c = red[0];
        g_fast = (nz == 0) ? 1 : 0;
    }
}

// ---------------------------------------------------------------------------
// Kernel 1: fused per-row tn + density + select (fast path).
//           Always writes g_tn (for fallback). 64 blocks x 256 threads.
// ---------------------------------------------------------------------------
__global__ void fused_kernel(const float* __restrict__ tp,
                             const float* __restrict__ b3,
                             float* __restrict__ out_density,
                             float* __restrict__ out_idx, int K)
{
    __shared__ SelShared ss;
    __shared__ float smin[256];
    __shared__ float smax[256];

    int row = blockIdx.x;
    int tid = threadIdx.x;
    const float* x = tp + row * N_PTS;

    float tv[4];
    float mn = INFINITY, mx = -INFINITY;
    #pragma unroll
    for (int sgi = 0; sgi < 4; sgi++) {
        float v = x[tid + 256 * sgi];
        tv[sgi] = v;
        mn = fminf(mn, v);
        mx = fmaxf(mx, v);
    }
    smin[tid] = mn; smax[tid] = mx;
    __syncthreads();
    for (int st = 128; st > 0; st >>= 1) {
        if (tid < st) {
            smin[tid] = fminf(smin[tid], smin[tid + st]);
            smax[tid] = fmaxf(smax[tid], smax[tid + st]);
        }
        __syncthreads();
    }
    float tmin = smin[0];
    float inv  = 1.0f / fmaxf(smax[0] - tmin, 1e-6f);

    int fast = g_fast;
    float c  = g_c;
    float b3v = b3[0];

    #pragma unroll
    for (int sgi = 0; sgi < 4; sgi++) {
        int i = tid + 256 * sgi;
        float t = (tv[sgi] - tmin) * inv;
        g_tn[row * N_PTS + i] = t;
        if (fast) {
            float v = fmaf(c, t, b3v);
            float d = fmaxf(v, 0.0f) + log1pf(expf(-fabsf(v)));
            ss.xs[i] = d;
            out_density[row * N_PTS + i] = d;
        }
    }
    if (!fast) return;
    __syncthreads();

    select_core(&ss, out_idx + row * K, K);
}

// ---------------------------------------------------------------------------
// Kernel 2: fallback full MLP (persistent; early-exits on fast path).
// ---------------------------------------------------------------------------
__global__ void mlp_kernel(const float* __restrict__ tn,
                           const float* __restrict__ W1, const float* __restrict__ b1,
                           const float* __restrict__ W2, const float* __restrict__ b2,
                           const float* __restrict__ W3, const float* __restrict__ b3,
                           float* __restrict__ out)
{
    if (g_fast) return;
    __shared__ float h1s[EPB][HID];
    int tid = threadIdx.x;

    for (int tile = blockIdx.x; tile < (B_ROWS * N_PTS) / EPB; tile += gridDim.x) {
        int base = tile * EPB;
        __syncthreads();
        #pragma unroll
        for (int idx = tid; idx < EPB * HID; idx += 256) {
            int e = idx >> 8;
            int k = idx & 255;
            float t = tn[base + e];
            h1s[e][k] = fmaxf(fmaf(t, W1[k], b1[k]), 0.0f);
        }
        __syncthreads();

        int j = tid;
        float acc[EPB];
        float bj = b2[j];
        #pragma unroll
        for (int e = 0; e < EPB; e++) acc[e] = bj;

        #pragma unroll 4
        for (int k = 0; k < HID; k += 4) {
            float w0 = W2[(k + 0) * HID + j];
            float w1 = W2[(k + 1) * HID + j];
            float w2 = W2[(k + 2) * HID + j];
            float w3 = W2[(k + 3) * HID + j];
            #pragma unroll
            for (int e = 0; e < EPB; e++) {
                float4 h = *reinterpret_cast<const float4*>(&h1s[e][k]);
                acc[e] = fmaf(h.x, w0, acc[e]);
                acc[e] = fmaf(h.y, w1, acc[e]);
                acc[e] = fmaf(h.z, w2, acc[e]);
                acc[e] = fmaf(h.w, w3, acc[e]);
            }
        }

        float w3j = W3[j];
        __syncthreads();
        #pragma unroll
        for (int e = 0; e < EPB; e++)
            h1s[e][tid] = fmaxf(acc[e], 0.0f) * w3j;
        __syncthreads();

        for (int st = 128; st > 0; st >>= 1) {
            if (tid < st) {
                #pragma unroll
                for (int e = 0; e < EPB; e++)
                    h1s[e][tid] += h1s[e][tid + st];
            }
            __syncthreads();
        }
        if (tid < EPB) {
            float v = h1s[tid][0] + b3[0];
            out[base + tid] = fmaxf(v, 0.0f) + log1pf(expf(-fabsf(v)));
        }
    }
}

// ---------------------------------------------------------------------------
// Kernel 3: fallback select (early-exits on fast path).
// ---------------------------------------------------------------------------
__global__ void select_fb_kernel(const float* __restrict__ density,
                                 float* __restrict__ out_idx, int K)
{
    if (g_fast) return;
    __shared__ SelShared ss;
    int row = blockIdx.x;
    int tid = threadIdx.x;
    #pragma unroll
    for (int sgi = 0; sgi < 4; sgi++) {
        int i = tid + 256 * sgi;
        ss.xs[i] = density[row * N_PTS + i];
    }
    __syncthreads();
    select_core(&ss, out_idx + row * K, K);
}

// ---------------------------------------------------------------------------
extern "C" void kernel_launch(void* const* d_in, const int* in_sizes, int n_in,
                              void* d_out, int out_size)
{
    const float* time_points = (const float*)d_in[0];
    const float* W1 = (const float*)d_in[2];
    const float* b1 = (const float*)d_in[3];
    const float* W2 = (const float*)d_in[4];
    const float* b2 = (const float*)d_in[5];
    const float* W3 = (const float*)d_in[6];
    const float* b3 = (const float*)d_in[7];

    float* out = (float*)d_out;
    float* out_density = out;
    float* out_indices = out + B_ROWS * N_PTS;

    int K = (out_size - B_ROWS * N_PTS) / B_ROWS;
    if (K < 1) K = 16;
    if (K > KMAX) K = KMAX;

    float* tn;
    cudaGetSymbolAddress((void**)&tn, g_tn);

    setup_kernel<<<1, 1024>>>(W1, b1, W2, b2, W3);
    fused_kernel<<<B_ROWS, 256>>>(time_points, b3, out_density, out_indices, K);
    mlp_kernel<<<512, 256>>>(tn, W1, b1, W2, b2, W3, b3, out_density);
    select_fb_kernel<<<B_ROWS, 256>>>(out_density, out_indices, K);
}